// round 10
// baseline (speedup 1.0000x reference)
#include <cuda_runtime.h>

#define IN_F   5
#define D_FC   32
#define D_H    64
#define NG     256      // 4*D_H gate rows
#define T_LEN  512
#define B_TOT  4096
#define NBLK   444      // 148 SMs * 3 blocks, single wave
#define BLOCK  128
#define CHUNK  16       // x staging chunk (timesteps)
#define NB_MAX 10       // 100 blocks get 10 batches, 344 get 9
#define XPAD   6        // x padded to 6 floats per timestep (u64-aligned)
#define LOG2E  1.4426950408889634f

// Precomputed fused input projection: W_comb [256][5], bias_comb [256]
__device__ float g_Wc[NG * IN_F];
__device__ float g_bc[NG];

// ---------------------------------------------------------------------------
// Setup: fold fc0 into LSTM input projection.
//   W_comb = W_ih @ W0 ; bias_c = W_ih @ b0 + b_ih + b_hh
// ---------------------------------------------------------------------------
__global__ void precompute_kernel(const float* __restrict__ W0,
                                  const float* __restrict__ b0,
                                  const float* __restrict__ W_ih,
                                  const float* __restrict__ b_ih,
                                  const float* __restrict__ b_hh)
{
    int r = blockIdx.x * blockDim.x + threadIdx.x;
    if (r >= NG) return;
    float wc[IN_F] = {0.f, 0.f, 0.f, 0.f, 0.f};
    float bc = b_ih[r] + b_hh[r];
    for (int m = 0; m < D_FC; ++m) {
        float wim = W_ih[r * D_FC + m];
        bc += wim * b0[m];
        #pragma unroll
        for (int k = 0; k < IN_F; ++k)
            wc[k] += wim * W0[m * IN_F + k];
    }
    #pragma unroll
    for (int k = 0; k < IN_F; ++k) g_Wc[r * IN_F + k] = wc[k];
    g_bc[r] = bc;
}

// ---------------------------------------------------------------------------
// Packed f32x2 helpers (Blackwell FFMA2 path)
// ---------------------------------------------------------------------------
typedef unsigned long long ull;

__device__ __forceinline__ ull fma2(ull a, ull b, ull c)
{
    ull d;
    asm("fma.rn.f32x2 %0, %1, %2, %3;" : "=l"(d) : "l"(a), "l"(b), "l"(c));
    return d;
}

__device__ __forceinline__ ull add2(ull a, ull b)
{
    ull d;
    asm("add.rn.f32x2 %0, %1, %2;" : "=l"(d) : "l"(a), "l"(b));
    return d;
}

__device__ __forceinline__ float2 u2f2(ull v)
{
    float2 r;
    asm("mov.b64 {%0, %1}, %2;" : "=f"(r.x), "=f"(r.y) : "l"(v));
    return r;
}

__device__ __forceinline__ ull pack2(float lo, float hi)
{
    ull v;
    asm("mov.b64 %0, {%1, %2};" : "=l"(v) : "f"(lo), "f"(hi));
    return v;
}

// ---------------------------------------------------------------------------
// Fused persistent LSTM kernel.
//   lane&1==0 (gs0): rows (j, j+128)  = (i, g)
//   lane&1==1 (gs1): rows (j+64,j+192)= (f, o)
//   Partner lanes exchange via shfl.bfly(1); c/h updated inline; one barrier
//   per step (h ping-pong). Dots(b+1) software-pipelined over epilogue(b).
// ---------------------------------------------------------------------------
__global__ void __launch_bounds__(BLOCK, 3)
lstm_kernel(const float* __restrict__ x,
            const float* __restrict__ W_hh,
            const float* __restrict__ Wo,
            const float* __restrict__ bo,
            float* __restrict__ out)
{
    __shared__ __align__(16) float h2[2][NB_MAX * D_H];            // 2 x 2.5 KB
    __shared__ float c_sh[NB_MAX * D_H];                            // 2.5 KB
    __shared__ __align__(16) float x_sh[NB_MAX * CHUNK * XPAD];     // 3.75 KB
    __shared__ float wo_sh[D_H];

    const int tid  = threadIdx.x;
    const int bid  = blockIdx.x;
    const int lane = tid & 31;
    const int warp = tid >> 5;
    const int gs   = lane & 1;                 // 0:(i,g)  1:(f,o)
    const int j    = warp * 16 + (lane >> 1);  // hidden unit

    // batch partition: 100 blocks * 10 + 344 blocks * 9 = 4096
    int nb, b0g;
    if (bid < 100) { nb = 10; b0g = bid * 10; }
    else           { nb = 9;  b0g = 1000 + (bid - 100) * 9; }

    // rows owned by this thread
    const int r0 = gs ? (j + 64)  : j;          // f : i
    const int r1 = gs ? (j + 192) : (j + 128);  // o : g

    // register-resident W_hh rows (packed f32x2 pairs)
    ull w0[D_H / 2], w1[D_H / 2];
    {
        const ull* p0 = (const ull*)(W_hh + r0 * D_H);
        const ull* p1 = (const ull*)(W_hh + r1 * D_H);
        #pragma unroll
        for (int i = 0; i < D_H / 2; ++i) { w0[i] = p0[i]; w1[i] = p1[i]; }
    }

    // fused input weights, packed (x padded to 6 -> 3 pairs, last hi = 0)
    ull wc0[3], wc1[3];
    {
        const float* a = g_Wc + r0 * IN_F;
        const float* b = g_Wc + r1 * IN_F;
        wc0[0] = pack2(a[0], a[1]); wc0[1] = pack2(a[2], a[3]); wc0[2] = pack2(a[4], 0.f);
        wc1[0] = pack2(b[0], b[1]); wc1[1] = pack2(b[2], b[3]); wc1[2] = pack2(b[4], 0.f);
    }
    const ull bc0p = pack2(g_bc[r0], 0.f);
    const ull bc1p = pack2(g_bc[r1], 0.f);

    // per-lane nonlinearity constants for acc1:
    //   gs0 needs tanh(a)    = 2*r - 1 with r = 1/(1+exp2(-2*log2e*a))
    //   gs1 needs sigmoid(a) = 1*r + 0 with r = 1/(1+exp2(  -log2e*a))
    const float kl = gs ? -LOG2E : -2.f * LOG2E;
    const float mm = gs ? 1.f : 2.f;
    const float ca = gs ? 0.f : -1.f;

    if (tid < D_H) wo_sh[tid] = Wo[tid];
    for (int i = tid; i < NB_MAX * D_H; i += BLOCK) {
        h2[0][i] = 0.f; h2[1][i] = 0.f; c_sh[i] = 0.f;
    }
    for (int i = tid; i < NB_MAX * CHUNK * XPAD; i += BLOCK) x_sh[i] = 0.f;
    __syncthreads();

    const int cj = j;  // c/h write index within a batch slice

    for (int t = 0; t < T_LEN; ++t) {
        // ---- stage x chunk (previous chunk fully consumed: end-of-step
        //      barrier of t-1 already passed)
        if ((t & (CHUNK - 1)) == 0) {
            #pragma unroll 1
            for (int i = tid; i < NB_MAX * CHUNK * IN_F; i += BLOCK) {
                int b  = i / (CHUNK * IN_F);
                int rm = i - b * (CHUNK * IN_F);
                int tt = rm / IN_F;
                int k  = rm - tt * IN_F;
                int gb = b0g + b;
                if (gb > B_TOT - 1) gb = B_TOT - 1;   // clamp (data unused)
                x_sh[(b * CHUNK + tt) * XPAD + k] =
                    x[((long long)gb * T_LEN + t + tt) * IN_F + k];
            }
            __syncthreads();
        }

        const int tslot = t & (CHUNK - 1);
        const float* hold = h2[t & 1];
        float*       hnew = h2[(t & 1) ^ 1];

        // ---------------- dot for one batch -> packed partial sums ----------
        #define DOT(B, O0, O1)                                                 \
        {                                                                      \
            const ulonglong2* hp = (const ulonglong2*)(hold + (B) * D_H);      \
            const ull* xp = (const ull*)(x_sh + ((B) * CHUNK + tslot) * XPAD); \
            ull xv0 = xp[0], xv1 = xp[1], xv2 = xp[2];                         \
            ull a00 = bc0p, a01 = 0ull, a10 = bc1p, a11 = 0ull;                \
            a00 = fma2(wc0[0], xv0, a00);  a10 = fma2(wc1[0], xv0, a10);       \
            a01 = fma2(wc0[1], xv1, a01);  a11 = fma2(wc1[1], xv1, a11);       \
            a00 = fma2(wc0[2], xv2, a00);  a10 = fma2(wc1[2], xv2, a10);       \
            _Pragma("unroll")                                                  \
            for (int i = 0; i < 16; ++i) {                                     \
                ulonglong2 hv = hp[i];                                         \
                a00 = fma2(w0[2 * i],     hv.x, a00);                          \
                a10 = fma2(w1[2 * i],     hv.x, a10);                          \
                a01 = fma2(w0[2 * i + 1], hv.y, a01);                          \
                a11 = fma2(w1[2 * i + 1], hv.y, a11);                          \
            }                                                                  \
            O0 = add2(a00, a01);  O1 = add2(a10, a11);                         \
        }

        // ---------------- epilogue for one batch ----------------------------
        #define EPI(B, P0, P1)                                                 \
        {                                                                      \
            float2 f0 = u2f2(P0), f1 = u2f2(P1);                               \
            float acc0 = f0.x + f0.y;                                          \
            float acc1 = f1.x + f1.y;                                          \
            float s0 = __fdividef(1.f, 1.f + exp2f(-LOG2E * acc0));            \
            float rr = __fdividef(1.f, 1.f + exp2f(kl * acc1));                \
            float vb = __fmaf_rn(mm, rr, ca);       /* gs0:tanh(g) gs1:sig(o)*/\
            float tt = s0 * vb;                     /* gs0: aig    gs1: junk */\
            float send1 = gs ? s0 : tt;             /* gs0: aig    gs1: sf   */\
            float x1 = __shfl_xor_sync(0xffffffffu, send1, 1);                 \
            float x2 = __shfl_xor_sync(0xffffffffu, vb, 1);                    \
            float cold = c_sh[(B) * D_H + cj];                                 \
            float cc = __fmaf_rn(x1, cold, tt);     /* gs0: sf*c + aig */      \
            float r2 = __fdividef(1.f, 1.f + exp2f(-2.f * LOG2E * cc));        \
            float th = __fmaf_rn(2.f, r2, -1.f);                               \
            if (!gs) {                                                         \
                c_sh[(B) * D_H + cj] = cc;                                     \
                hnew[(B) * D_H + cj] = x2 * th;     /* so * tanh(c) */         \
            }                                                                  \
        }

        // ---- software-pipelined batch loop: dots(b+1) overlaps epi(b)
        ull p0, p1, n0, n1;
        DOT(0, p0, p1);
        #pragma unroll
        for (int b = 1; b < 9; ++b) {
            DOT(b, n0, n1);
            EPI(b - 1, p0, p1);
            p0 = n0; p1 = n1;
        }
        if (nb > 9) {
            DOT(9, n0, n1);
            EPI(8, p0, p1);
            EPI(9, n0, n1);
        } else {
            EPI(8, p0, p1);
        }

        #undef DOT
        #undef EPI

        __syncthreads();   // hnew complete before next step reads it
    }

    // ---- output: out[b] = Wo @ h_last + bo  (final h lives in h2[0])
    if (tid < nb) {
        float acc = bo[0];
        #pragma unroll
        for (int k = 0; k < D_H; ++k)
            acc = __fmaf_rn(wo_sh[k], h2[0][tid * D_H + k], acc);
        out[b0g + tid] = acc;
    }
}

// ---------------------------------------------------------------------------
// Harness entry. Inputs (metadata order):
//   0:x 1:W0 2:b0 3:W_ih 4:W_hh 5:b_ih 6:b_hh 7:Wo 8:bo ; out: float[4096]
// ---------------------------------------------------------------------------
extern "C" void kernel_launch(void* const* d_in, const int* in_sizes, int n_in,
                              void* d_out, int out_size)
{
    (void)in_sizes; (void)n_in; (void)out_size;
    const float* x    = (const float*)d_in[0];
    const float* W0   = (const float*)d_in[1];
    const float* b0   = (const float*)d_in[2];
    const float* W_ih = (const float*)d_in[3];
    const float* W_hh = (const float*)d_in[4];
    const float* b_ih = (const float*)d_in[5];
    const float* b_hh = (const float*)d_in[6];
    const float* Wo   = (const float*)d_in[7];
    const float* bo   = (const float*)d_in[8];

    precompute_kernel<<<1, NG>>>(W0, b0, W_ih, b_ih, b_hh);
    lstm_kernel<<<NBLK, BLOCK>>>(x, W_hh, Wo, bo, (float*)d_out);
}

// round 13
// speedup vs baseline: 1.0904x; 1.0904x over previous
#include <cuda_runtime.h>

#define IN_F   5
#define D_FC   32
#define D_H    64
#define NG     256      // 4*D_H gate rows
#define T_LEN  512
#define B_TOT  4096
#define NBLK   444      // 148 SMs * 3 blocks, single wave
#define BLOCK  128
#define CHUNK  16       // x staging chunk (timesteps)
#define NB_MAX 10       // 100 blocks get 10 batches, 344 get 9
#define XPAD   6        // x padded to 6 floats: [x0..x4, 1.0]
#define LOG2E  1.4426950408889634f

// Prescaled fused input projection + prescaled W_hh.
//   g_Wc[r][0..4] = s_r * (W_ih@W0)[r],  g_Wc[r][5] = s_r * bias_comb[r]
//   g_Whh[r][:]   = s_r * W_hh[r][:]
//   s_r = -2*log2e for tanh rows (g: 128..191), -log2e otherwise (sigmoid).
// Gate rows feed only the nonlinearities, so prescaling is exact:
//   sigmoid(a) = rcp(1 + ex2(-log2e*a)),  tanh(a) = 2*rcp(1+ex2(-2log2e*a))-1.
__device__ float g_Wc[NG * XPAD];
__device__ float g_Whh[NG * D_H];

// ---------------------------------------------------------------------------
// Setup: fold fc0 into LSTM input projection, prescale everything.
// ---------------------------------------------------------------------------
__global__ void precompute_kernel(const float* __restrict__ W0,
                                  const float* __restrict__ b0,
                                  const float* __restrict__ W_ih,
                                  const float* __restrict__ b_ih,
                                  const float* __restrict__ b_hh,
                                  const float* __restrict__ W_hh)
{
    int r = blockIdx.x * blockDim.x + threadIdx.x;
    if (r >= NG) return;
    float wc[IN_F] = {0.f, 0.f, 0.f, 0.f, 0.f};
    float bc = b_ih[r] + b_hh[r];
    for (int m = 0; m < D_FC; ++m) {
        float wim = W_ih[r * D_FC + m];
        bc += wim * b0[m];
        #pragma unroll
        for (int k = 0; k < IN_F; ++k)
            wc[k] += wim * W0[m * IN_F + k];
    }
    const float s = (r >= 128 && r < 192) ? (-2.f * LOG2E) : (-LOG2E);
    #pragma unroll
    for (int k = 0; k < IN_F; ++k) g_Wc[r * XPAD + k] = s * wc[k];
    g_Wc[r * XPAD + 5] = s * bc;
    for (int k = 0; k < D_H; ++k)
        g_Whh[r * D_H + k] = s * W_hh[r * D_H + k];
}

// ---------------------------------------------------------------------------
// Packed f32x2 + MUFU helpers
// ---------------------------------------------------------------------------
typedef unsigned long long ull;

__device__ __forceinline__ ull fma2(ull a, ull b, ull c)
{
    ull d;
    asm("fma.rn.f32x2 %0, %1, %2, %3;" : "=l"(d) : "l"(a), "l"(b), "l"(c));
    return d;
}

__device__ __forceinline__ ull add2(ull a, ull b)
{
    ull d;
    asm("add.rn.f32x2 %0, %1, %2;" : "=l"(d) : "l"(a), "l"(b));
    return d;
}

__device__ __forceinline__ float2 u2f2(ull v)
{
    float2 r;
    asm("mov.b64 {%0, %1}, %2;" : "=f"(r.x), "=f"(r.y) : "l"(v));
    return r;
}

__device__ __forceinline__ ull pack2(float lo, float hi)
{
    ull v;
    asm("mov.b64 %0, {%1, %2};" : "=l"(v) : "f"(lo), "f"(hi));
    return v;
}

__device__ __forceinline__ float ex2_(float x)
{
    float y;
    asm("ex2.approx.ftz.f32 %0, %1;" : "=f"(y) : "f"(x));
    return y;
}

__device__ __forceinline__ float rcp_(float x)
{
    float y;
    asm("rcp.approx.ftz.f32 %0, %1;" : "=f"(y) : "f"(x));
    return y;
}

__device__ __forceinline__ float tanh_(float x)   // true-scale tanh
{
    float e = ex2_(-2.f * LOG2E * x);
    return __fmaf_rn(2.f, rcp_(1.f + e), -1.f);
}

// ---------------------------------------------------------------------------
// Fused persistent LSTM kernel (R8 structure + pipelined phase-1 epilogue).
//   half==0 threads own rows (j, j+128)  = (i, g) -> emit sigmoid(i)*tanh(g)
//   half==1 threads own rows (j+64,j+192)= (f, o) -> emit sigmoid(f),sigmoid(o)
//   Phase 2: c = sf*c + aig ; h = so*tanh(c)   (c in smem)
// ---------------------------------------------------------------------------
__global__ void __launch_bounds__(BLOCK, 3)
lstm_kernel(const float* __restrict__ x,
            const float* __restrict__ Wo,
            const float* __restrict__ bo,
            float* __restrict__ out)
{
    __shared__ __align__(16) float h_sh[NB_MAX * D_H];              // 2.5 KB
    __shared__ float c_sh[NB_MAX * D_H];                             // 2.5 KB
    __shared__ float aig_sh[NB_MAX * D_H];                           // 2.5 KB
    __shared__ float sf_sh[NB_MAX * D_H];                            // 2.5 KB
    __shared__ float so_sh[NB_MAX * D_H];                            // 2.5 KB
    __shared__ __align__(16) float x_sh[NB_MAX * CHUNK * XPAD];      // 3.75 KB
    __shared__ float wo_sh[D_H];

    const int tid  = threadIdx.x;
    const int bid  = blockIdx.x;
    const int rg   = tid & 63;
    const int half = tid >> 6;        // uniform per warp (warps 0,1 / 2,3)

    // batch partition: 100 blocks * 10 + 344 blocks * 9 = 4096
    int nb, b0g;
    if (bid < 100) { nb = 10; b0g = bid * 10; }
    else           { nb = 9;  b0g = 1000 + (bid - 100) * 9; }

    // rows owned by this thread
    const int r0 = half ? (rg + 64)  : rg;          // f : i   (sigmoid rows)
    const int r1 = half ? (rg + 192) : (rg + 128);  // o : g

    // register-resident prescaled W_hh rows (packed f32x2 pairs)
    ull w0[D_H / 2], w1[D_H / 2];
    {
        const ull* p0 = (const ull*)(g_Whh + r0 * D_H);
        const ull* p1 = (const ull*)(g_Whh + r1 * D_H);
        #pragma unroll
        for (int i = 0; i < D_H / 2; ++i) { w0[i] = p0[i]; w1[i] = p1[i]; }
    }

    // prescaled input weights + bias folded at lane 5 (x_sh[...,5] == 1.0)
    ull wc0[3], wc1[3];
    {
        const ull* a = (const ull*)(g_Wc + r0 * XPAD);  // 24B rows, 8B aligned
        const ull* b = (const ull*)(g_Wc + r1 * XPAD);
        wc0[0] = a[0]; wc0[1] = a[1]; wc0[2] = a[2];
        wc1[0] = b[0]; wc1[1] = b[1]; wc1[2] = b[2];
    }

    // per-half nonlinearity constants for acc1 (vb = mm*rcp(1+ex2(acc1)) + ca)
    const float mm = half ? 1.f : 2.f;
    const float ca = half ? 0.f : -1.f;

    if (tid < D_H) wo_sh[tid] = Wo[tid];
    for (int i = tid; i < NB_MAX * D_H; i += BLOCK) {
        h_sh[i] = 0.f; c_sh[i] = 0.f;
        aig_sh[i] = 0.f; sf_sh[i] = 0.f; so_sh[i] = 0.f;
    }
    for (int i = tid; i < NB_MAX * CHUNK * XPAD; i += BLOCK)
        x_sh[i] = ((i % XPAD) == 5) ? 1.f : 0.f;   // constant-1 bias lane
    __syncthreads();

    for (int t = 0; t < T_LEN; ++t) {
        // ---- stage x chunk (previous chunk fully consumed before this point)
        if ((t & (CHUNK - 1)) == 0) {
            #pragma unroll 1
            for (int i = tid; i < NB_MAX * CHUNK * IN_F; i += BLOCK) {
                int b  = i / (CHUNK * IN_F);
                int rm = i - b * (CHUNK * IN_F);
                int tt = rm / IN_F;
                int k  = rm - tt * IN_F;
                int gb = b0g + b;
                if (gb > B_TOT - 1) gb = B_TOT - 1;   // clamp (data unused)
                x_sh[(b * CHUNK + tt) * XPAD + k] =
                    x[((long long)gb * T_LEN + t + tt) * IN_F + k];
            }
            __syncthreads();
        }

        const int tslot = t & (CHUNK - 1);

        // dot for one batch -> reduced scalar pair (prescaled pre-activations)
        #define DOT(B, A0, A1)                                                 \
        {                                                                      \
            const ulonglong2* hp = (const ulonglong2*)(h_sh + (B) * D_H);      \
            const ull* xp = (const ull*)(x_sh + ((B) * CHUNK + tslot) * XPAD); \
            ull xv0 = xp[0], xv1 = xp[1], xv2 = xp[2];                         \
            ull a00 = fma2(wc0[0], xv0, 0ull);                                 \
            ull a10 = fma2(wc1[0], xv0, 0ull);                                 \
            ull a01 = fma2(wc0[1], xv1, 0ull);                                 \
            ull a11 = fma2(wc1[1], xv1, 0ull);                                 \
            a00 = fma2(wc0[2], xv2, a00);                                      \
            a10 = fma2(wc1[2], xv2, a10);                                      \
            _Pragma("unroll")                                                  \
            for (int i = 0; i < 16; ++i) {                                     \
                ulonglong2 hv = hp[i];                 /* broadcast LDS.128 */ \
                a00 = fma2(w0[2 * i],     hv.x, a00);                          \
                a10 = fma2(w1[2 * i],     hv.x, a10);                          \
                a01 = fma2(w0[2 * i + 1], hv.y, a01);                          \
                a11 = fma2(w1[2 * i + 1], hv.y, a11);                          \
            }                                                                  \
            ull s0_ = add2(a00, a01), s1_ = add2(a10, a11);                    \
            float2 f0 = u2f2(s0_), f1 = u2f2(s1_);                             \
            A0 = f0.x + f0.y;                                                  \
            A1 = f1.x + f1.y;                                                  \
        }

        // epilogue for one batch (MUFU chains; prescaled -> no FMUL first)
        #define EPI(B, A0, A1)                                                 \
        {                                                                      \
            float e0 = ex2_(A0);                                               \
            float e1 = ex2_(A1);                                               \
            float s0 = rcp_(1.f + e0);          /* sigmoid(i) / sigmoid(f) */  \
            float rr = rcp_(1.f + e1);                                         \
            float vb = __fmaf_rn(mm, rr, ca);   /* tanh(g) / sigmoid(o)   */   \
            if (half == 0) {                                                   \
                aig_sh[(B) * D_H + rg] = s0 * vb;                              \
            } else {                                                           \
                sf_sh[(B) * D_H + rg] = s0;                                    \
                so_sh[(B) * D_H + rg] = vb;                                    \
            }                                                                  \
        }

        // ---- phase 1, pipelined: EPI(b-1) interleaves with DOT(b) FMAs
        float p0, p1;
        DOT(0, p0, p1);
        #pragma unroll 1
        for (int b = 1; b < nb; ++b) {
            float n0, n1;
            DOT(b, n0, n1);
            EPI(b - 1, p0, p1);
            p0 = n0; p1 = n1;
        }
        EPI(nb - 1, p0, p1);
        #undef DOT
        #undef EPI
        __syncthreads();

        // ---- phase 2: state update (1 tanh per unit, c in smem)
        #pragma unroll
        for (int s = 0; s < (NB_MAX * D_H + BLOCK - 1) / BLOCK; ++s) {
            int u = tid + BLOCK * s;
            if (u < nb * D_H) {
                float a  = aig_sh[u];
                float sf = sf_sh[u];
                float so = so_sh[u];
                float cc = __fmaf_rn(sf, c_sh[u], a);
                c_sh[u] = cc;
                h_sh[u] = so * tanh_(cc);
            }
        }
        __syncthreads();
    }

    // ---- output: out[b] = Wo @ h_last + bo
    if (tid < nb) {
        float acc = bo[0];
        #pragma unroll
        for (int k = 0; k < D_H; ++k)
            acc = __fmaf_rn(wo_sh[k], h_sh[tid * D_H + k], acc);
        out[b0g + tid] = acc;
    }
}

// ---------------------------------------------------------------------------
// Harness entry. Inputs (metadata order):
//   0:x 1:W0 2:b0 3:W_ih 4:W_hh 5:b_ih 6:b_hh 7:Wo 8:bo ; out: float[4096]
// ---------------------------------------------------------------------------
extern "C" void kernel_launch(void* const* d_in, const int* in_sizes, int n_in,
                              void* d_out, int out_size)
{
    (void)in_sizes; (void)n_in; (void)out_size;
    const float* x    = (const float*)d_in[0];
    const float* W0   = (const float*)d_in[1];
    const float* b0   = (const float*)d_in[2];
    const float* W_ih = (const float*)d_in[3];
    const float* W_hh = (const float*)d_in[4];
    const float* b_ih = (const float*)d_in[5];
    const float* b_hh = (const float*)d_in[6];
    const float* Wo   = (const float*)d_in[7];
    const float* bo   = (const float*)d_in[8];

    precompute_kernel<<<1, NG>>>(W0, b0, W_ih, b_ih, b_hh, W_hh);
    lstm_kernel<<<NBLK, BLOCK>>>(x, Wo, bo, (float*)d_out);
}